// round 14
// baseline (speedup 1.0000x reference)
#include <cuda_runtime.h>
#include <cuda_fp16.h>
#include <math.h>
#include <stdint.h>

#define B_   4
#define S_   2048
#define D_   2048
#define H_   16
#define KVH_ 8
#define HD_  128
#define MSZ  (B_ * S_)          // 8192

// ---------------- scratch (device globals; no allocation allowed) ----------------
__device__ __half g_xhi[(size_t)MSZ * D_];
__device__ __half g_xlo[(size_t)MSZ * D_];
__device__ __half g_wqh[(size_t)D_ * D_];
__device__ __half g_wkh[(size_t)D_ * KVH_ * HD_];
__device__ __half g_wvh[(size_t)D_ * KVH_ * HD_];
__device__ __half g_woh[(size_t)D_ * D_];
__device__ __half g_athi[(size_t)MSZ * D_];
__device__ __half g_atlo[(size_t)MSZ * D_];

__device__ __half g_qhi[(size_t)MSZ * D_];
__device__ __half g_khi[(size_t)MSZ * KVH_ * HD_];
__device__ __half g_vthi[(size_t)MSZ * KVH_ * HD_];     // [b][hk][d][s]

// ================= helpers (baseline PTX only) =================
__device__ __forceinline__ uint32_t smem_u32(const void* p) {
    uint32_t a;
    asm("{ .reg .u64 t; cvta.to.shared.u64 t, %1; cvt.u32.u64 %0, t; }" : "=r"(a) : "l"(p));
    return a;
}
__device__ __forceinline__ void cp_async16(uint32_t dst, const void* src) {
    asm volatile("cp.async.cg.shared.global [%0], [%1], 16;" :: "r"(dst), "l"(src) : "memory");
}
__device__ __forceinline__ void ldmatrix_x4(uint32_t* r, uint32_t addr) {
    asm volatile("ldmatrix.sync.aligned.m8n8.x4.shared.b16 {%0,%1,%2,%3}, [%4];"
                 : "=r"(r[0]), "=r"(r[1]), "=r"(r[2]), "=r"(r[3]) : "r"(addr));
}
__device__ __forceinline__ void mma_f16(float* c, const uint32_t* a, uint32_t b0, uint32_t b1) {
    asm volatile("mma.sync.aligned.m16n8k16.row.col.f32.f16.f16.f32 "
                 "{%0,%1,%2,%3}, {%4,%5,%6,%7}, {%8,%9}, {%0,%1,%2,%3};"
                 : "+f"(c[0]), "+f"(c[1]), "+f"(c[2]), "+f"(c[3])
                 : "r"(a[0]), "r"(a[1]), "r"(a[2]), "r"(a[3]), "r"(b0), "r"(b1));
}
__device__ __forceinline__ float ex2f(float x) {
    float y;
    asm("ex2.approx.ftz.f32 %0, %1;" : "=f"(y) : "f"(x));
    return y;
}
__device__ __forceinline__ uint32_t pack_h2(float f0, float f1) {
    uint32_t r;
    asm("cvt.rn.f16x2.f32 %0, %1, %2;" : "=r"(r) : "f"(f1), "f"(f0));
    return r;
}
__device__ __forceinline__ void store_split2h(__half* hi, __half* lo,
                                              size_t off, float f0, float f1) {
    __half h0 = __float2half_rn(f0), h1 = __float2half_rn(f1);
    *(__half2*)(hi + off) = __halves2half2(h0, h1);
    *(__half2*)(lo + off) = __halves2half2(
        __float2half_rn(f0 - __half2float(h0)),
        __float2half_rn(f1 - __half2float(h1)));
}

// ================= fused conversions (ONE launch) =================
// z=0: wq transpose+round, z=1: wo, z=2: wk, z=3: wv, z=4: x hi/lo split.
// block (32,8); grid (64, 256, 5); weight sections guard their tile ranges.
__global__ __launch_bounds__(256) void convert_all(const float* __restrict__ x,
                                                   const float* __restrict__ wq,
                                                   const float* __restrict__ wk,
                                                   const float* __restrict__ wv,
                                                   const float* __restrict__ wo,
                                                   __half* __restrict__ xhi,
                                                   __half* __restrict__ xlo,
                                                   __half* __restrict__ wqh,
                                                   __half* __restrict__ wkh,
                                                   __half* __restrict__ wvh,
                                                   __half* __restrict__ woh) {
    const int z = blockIdx.z;
    const int xq = threadIdx.x, y = threadIdx.y;
    if (z == 4) {
        // x split: [8192, 2048] elementwise
        int r0 = blockIdx.y * 32, c0 = blockIdx.x * 32;
#pragma unroll
        for (int i = 0; i < 32; i += 8) {
            size_t idx = (size_t)(r0 + y + i) * D_ + c0 + xq;
            float f = x[idx];
            __half h = __float2half_rn(f);
            xhi[idx] = h;
            xlo[idx] = __float2half_rn(f - __half2float(h));
        }
        return;
    }
    const float* W; __half* O; int Nd;
    if (z == 0)      { W = wq; O = wqh; Nd = D_; }
    else if (z == 1) { W = wo; O = woh; Nd = D_; }
    else if (z == 2) { W = wk; O = wkh; Nd = KVH_ * HD_; }
    else             { W = wv; O = wvh; Nd = KVH_ * HD_; }
    if (blockIdx.y >= 64u || blockIdx.x >= (unsigned)(Nd / 32)) return;

    __shared__ float t[32][33];
    int k0 = blockIdx.y * 32, n0 = blockIdx.x * 32;
#pragma unroll
    for (int i = 0; i < 32; i += 8)
        t[y + i][xq] = W[(size_t)(k0 + y + i) * Nd + n0 + xq];
    __syncthreads();
#pragma unroll
    for (int i = 0; i < 32; i += 8)
        O[(size_t)(n0 + y + i) * D_ + k0 + xq] = __float2half_rn(t[xq][y + i]);
}

// ================= 2-pass fp16 GEMM: C = (Ahi+Alo)·Bhi^T =================
// mode 0: fp32 C. mode 1: RoPE(+scale) epilogue -> fp16 (lo optional). mode 2: V^T fp16.
#define TILE_B   10240          // 128 rows x 80 bytes
#define STAGE2_B (3 * TILE_B)   // Ah, Al, Bh
#define GEMM_SMEM (2 * STAGE2_B)

__global__ __launch_bounds__(256) void gemm2(const __half* __restrict__ Ahi,
                                             const __half* __restrict__ Alo,
                                             const __half* __restrict__ Bh,
                                             float* __restrict__ C,
                                             __half* __restrict__ Ohi,
                                             __half* __restrict__ Olo,
                                             const float* __restrict__ co,
                                             const float* __restrict__ si,
                                             float scale,
                                             int M, int N, int K, int mode) {
    extern __shared__ __align__(128) char smh[];
    const int tid = threadIdx.x, lane = tid & 31, wid = tid >> 5;
    const int m0 = blockIdx.y * 128, n0 = blockIdx.x * 128;
    const int wm = (wid & 3) * 32, wn = (wid >> 2) * 64;
    const uint32_t sb = smem_u32(smh);

    const __half* gsrc[3];
    gsrc[0] = Ahi + (size_t)m0 * K;
    gsrc[1] = Alo + (size_t)m0 * K;
    gsrc[2] = Bh + (size_t)n0 * K;

    auto load_chunk = [&](int c, int s) {
        const uint32_t st = sb + s * STAGE2_B;
#pragma unroll
        for (int t = 0; t < 6; ++t) {
            int idx = t * 256 + tid;
            int tile = idx >> 9;
            int r = (idx >> 2) & 127;
            int seg = idx & 3;
            uint32_t dst = st + tile * TILE_B + r * 80 + seg * 16;
            cp_async16(dst, gsrc[tile] + (size_t)r * K + c * 32 + seg * 8);
        }
        asm volatile("cp.async.commit_group;" ::: "memory");
    };

    float acc[2][8][4];
#pragma unroll
    for (int mf = 0; mf < 2; ++mf)
#pragma unroll
        for (int nf = 0; nf < 8; ++nf)
#pragma unroll
            for (int e = 0; e < 4; ++e) acc[mf][nf][e] = 0.f;

    const int nch = K / 32;
    load_chunk(0, 0);
    load_chunk(1, 1);

    for (int i = 0; i < nch; ++i) {
        const int s = i & 1;
        if (i + 1 < nch) asm volatile("cp.async.wait_group 1;" ::: "memory");
        else             asm volatile("cp.async.wait_group 0;" ::: "memory");
        __syncthreads();

        const uint32_t st = sb + s * STAGE2_B;
#pragma unroll
        for (int k16 = 0; k16 < 2; ++k16) {
            uint32_t ah[2][4], al[2][4];
#pragma unroll
            for (int mf = 0; mf < 2; ++mf) {
                int rowA = wm + mf * 16 + (lane & 15);
                int kA = k16 * 16 + ((lane >> 4) << 3);
                uint32_t off = (uint32_t)(rowA * 80 + kA * 2);
                ldmatrix_x4(ah[mf], st + off);
                ldmatrix_x4(al[mf], st + TILE_B + off);
            }
            uint32_t bh[4][4];
#pragma unroll
            for (int nf2 = 0; nf2 < 4; ++nf2) {
                int rowB = wn + nf2 * 16 + (lane & 7) + ((lane >> 4) << 3);
                int kB = k16 * 16 + (((lane >> 3) & 1) << 3);
                uint32_t off = (uint32_t)(rowB * 80 + kB * 2);
                ldmatrix_x4(bh[nf2], st + 2 * TILE_B + off);
            }
#pragma unroll
            for (int mf = 0; mf < 2; ++mf)
#pragma unroll
                for (int nf = 0; nf < 8; ++nf) {
                    uint32_t b0 = bh[nf >> 1][(nf & 1) * 2], b1 = bh[nf >> 1][(nf & 1) * 2 + 1];
                    mma_f16(acc[mf][nf], ah[mf], b0, b1);
                    mma_f16(acc[mf][nf], al[mf], b0, b1);
                }
        }
        __syncthreads();
        if (i + 2 < nch) load_chunk(i + 2, s);
    }

    if (mode == 0) {
#pragma unroll
        for (int mf = 0; mf < 2; ++mf) {
            int row = m0 + wm + mf * 16 + (lane >> 2);
#pragma unroll
            for (int nf = 0; nf < 8; ++nf) {
                int col = n0 + wn + nf * 8 + (lane & 3) * 2;
                *(float2*)&C[(size_t)row * N + col] = make_float2(acc[mf][nf][0], acc[mf][nf][1]);
                *(float2*)&C[(size_t)(row + 8) * N + col] = make_float2(acc[mf][nf][2], acc[mf][nf][3]);
            }
        }
    } else if (mode == 1) {
        // RoPE + scale epilogue; store hi (and lo if Olo != null)
#pragma unroll
        for (int mf = 0; mf < 2; ++mf) {
            int row = m0 + wm + mf * 16 + (lane >> 2);
            int s0 = row & (S_ - 1);
            int s1 = (row + 8) & (S_ - 1);
#pragma unroll
            for (int nf = 0; nf < 8; ++nf) {
                int col = n0 + wn + nf * 8 + (lane & 3) * 2;
                int fi = (col & (HD_ - 1)) >> 1;
                float c0 = co[s0 * 64 + fi], sn0 = si[s0 * 64 + fi];
                float c1 = co[s1 * 64 + fi], sn1 = si[s1 * 64 + fi];
                float a0 = acc[mf][nf][0], a1 = acc[mf][nf][1];
                float b0 = acc[mf][nf][2], b1 = acc[mf][nf][3];
                float r00 = (a0 * c0 - a1 * sn0) * scale, r01 = (a0 * sn0 + a1 * c0) * scale;
                float r10 = (b0 * c1 - b1 * sn1) * scale, r11 = (b0 * sn1 + b1 * c1) * scale;
                if (Olo) {
                    store_split2h(Ohi, Olo, (size_t)row * N + col, r00, r01);
                    store_split2h(Ohi, Olo, (size_t)(row + 8) * N + col, r10, r11);
                } else {
                    *(uint32_t*)((__half*)Ohi + (size_t)row * N + col) = pack_h2(r00, r01);
                    *(uint32_t*)((__half*)Ohi + (size_t)(row + 8) * N + col) = pack_h2(r10, r11);
                }
            }
        }
    } else {
        // mode 2: V^T epilogue — acc(row=bs token, col=hk*128+d) -> Ohi[b][hk][d][s]
#pragma unroll
        for (int mf = 0; mf < 2; ++mf) {
            int row = m0 + wm + mf * 16 + (lane >> 2);
#pragma unroll
            for (int rr = 0; rr < 2; ++rr) {
                int r = row + rr * 8;
                int bb = r >> 11, ss = r & (S_ - 1);
#pragma unroll
                for (int nf = 0; nf < 8; ++nf) {
                    int col = n0 + wn + nf * 8 + (lane & 3) * 2;
                    int hk = col >> 7, d = col & (HD_ - 1);
                    size_t base = (((size_t)bb * KVH_ + hk) * HD_ + d) * S_ + ss;
                    Ohi[base]      = __float2half_rn(acc[mf][nf][rr * 2 + 0]);
                    Ohi[base + S_] = __float2half_rn(acc[mf][nf][rr * 2 + 1]);   // d+1 row
                }
            }
        }
    }
}

// ================= flash attention v5: 64 q-rows/CTA, 2 CTAs/SM =================
// CTA: 128 threads (4 warps), 64 q-rows x one (b,h). KV tiles 64-wide, 3-stage, 1 sync/tile.
#define FK_ST 272               // K row stride bytes (128 halves + 8 pad)
#define FV_ST 144               // V^T row stride bytes (64 halves + 8 pad)
#define SK_HI 17408             // 64 * 272
#define SV_HI 18432             // 128 * 144
#define FSTAGE (SK_HI + SV_HI)  // 35840
#define NSTG 3
#define FLASH_SMEM (NSTG * FSTAGE)   // 107520 -> 2 CTAs/SM

__global__ __launch_bounds__(128) void flash_mma(
    const __half* __restrict__ qhi,
    const __half* __restrict__ khi,
    const __half* __restrict__ vthi,
    __half* __restrict__ athi, __half* __restrict__ atlo) {
    extern __shared__ __align__(128) char smc[];
    const uint32_t sb = smem_u32(smc);
    const int tid = threadIdx.x, lane = tid & 31, w = tid >> 5;   // w: 0..3
    const int qt = (int)gridDim.x - 1 - (int)blockIdx.x;          // heavy CTAs first
    const int h = blockIdx.y, b = blockIdx.z, hk = h >> 1;
    const int q0 = qt * 64;
    const int ntiles = qt + 1;

    auto load_tile = [&](int j, int s) {
        const uint32_t stb = sb + s * FSTAGE;
#pragma unroll
        for (int t = 0; t < 8; ++t) {
            int idx = t * 128 + tid;          // 0..1023 : 64 rows x 16 segs
            int r = idx >> 4, seg = idx & 15;
            size_t go = (((size_t)b * S_ + j * 64 + r) * KVH_ + hk) * HD_ + seg * 8;
            cp_async16(stb + (uint32_t)(r * FK_ST + seg * 16), khi + go);
        }
#pragma unroll
        for (int t = 0; t < 8; ++t) {
            int idx = t * 128 + tid;          // 0..1023 : 128 d-rows x 8 segs
            int dd = idx >> 3, seg = idx & 7;
            size_t go = (((size_t)b * KVH_ + hk) * HD_ + dd) * S_ + j * 64 + seg * 8;
            cp_async16(stb + SK_HI + (uint32_t)(dd * FV_ST + seg * 16), vthi + go);
        }
        asm volatile("cp.async.commit_group;" ::: "memory");
    };

    // ---- Q hi load (64 rows) into buffer 0, pull fragments to registers ----
#pragma unroll
    for (int t = 0; t < 8; ++t) {
        int idx = t * 128 + tid;
        int r = idx >> 4, seg = idx & 15;
        size_t go = (((size_t)b * S_ + q0 + r) * H_ + h) * HD_ + seg * 8;
        cp_async16(sb + (uint32_t)(r * FK_ST + seg * 16), qhi + go);
    }
    asm volatile("cp.async.commit_group;" ::: "memory");
    asm volatile("cp.async.wait_group 0;" ::: "memory");
    __syncthreads();
    uint32_t qh[8][4];
#pragma unroll
    for (int k16 = 0; k16 < 8; ++k16) {
        uint32_t offA = (uint32_t)((w * 16 + (lane & 15)) * FK_ST +
                                   (k16 * 16 + ((lane >> 4) << 3)) * 2);
        ldmatrix_x4(qh[k16], sb + offA);
    }
    __syncthreads();   // buffer 0 drained before tile 0 load reuses it

    load_tile(0, 0);
    if (ntiles > 1) load_tile(1, 1);

    float o[16][4];
#pragma unroll
    for (int nf = 0; nf < 16; ++nf)
#pragma unroll
        for (int e = 0; e < 4; ++e) o[nf][e] = 0.f;
    float mA = -1e30f, mB = -1e30f, lA = 0.f, lB = 0.f;   // l: per-lane partials

    for (int i = 0; i < ntiles; ++i) {
        if (i + 1 < ntiles) asm volatile("cp.async.wait_group 1;" ::: "memory");
        else                asm volatile("cp.async.wait_group 0;" ::: "memory");
        __syncthreads();
        if (i + 2 < ntiles) load_tile(i + 2, (i + 2) % NSTG);

        const uint32_t st = sb + (i % NSTG) * FSTAGE;

        // ---- S = Qh·Kh^T (1-pass, 64 cols) ----
        float c[8][4];
#pragma unroll
        for (int nf = 0; nf < 8; ++nf)
#pragma unroll
            for (int e = 0; e < 4; ++e) c[nf][e] = 0.f;

#pragma unroll
        for (int k16 = 0; k16 < 8; ++k16) {
#pragma unroll
            for (int g = 0; g < 4; ++g) {
                uint32_t bh[4];
                uint32_t offB = (uint32_t)((g * 16 + (lane & 7) + ((lane >> 4) << 3)) * FK_ST +
                                           (k16 * 16 + (((lane >> 3) & 1) << 3)) * 2);
                ldmatrix_x4(bh, st + offB);
                mma_f16(c[g * 2], qh[k16], bh[0], bh[1]);
                mma_f16(c[g * 2 + 1], qh[k16], bh[2], bh[3]);
            }
        }

        // ---- causal mask (diagonal tile only) ----
        if (i == qt) {
            int rowA = q0 + w * 16 + (lane >> 2);
            int colb = i * 64 + (lane & 3) * 2;
#pragma unroll
            for (int nf = 0; nf < 8; ++nf) {
                int c0 = colb + nf * 8, c1 = c0 + 1;
                if (c0 > rowA) c[nf][0] = -1e30f;
                if (c1 > rowA) c[nf][1] = -1e30f;
                if (c0 > rowA + 8) c[nf][2] = -1e30f;
                if (c1 > rowA + 8) c[nf][3] = -1e30f;
            }
        }

        // ---- online softmax (exp2 domain); l kept as per-lane partials ----
        float mtA = -1e30f, mtB = -1e30f;
#pragma unroll
        for (int nf = 0; nf < 8; ++nf) {
            mtA = fmaxf(mtA, fmaxf(c[nf][0], c[nf][1]));
            mtB = fmaxf(mtB, fmaxf(c[nf][2], c[nf][3]));
        }
        mtA = fmaxf(mtA, __shfl_xor_sync(0xffffffffu, mtA, 1));
        mtA = fmaxf(mtA, __shfl_xor_sync(0xffffffffu, mtA, 2));
        mtB = fmaxf(mtB, __shfl_xor_sync(0xffffffffu, mtB, 1));
        mtB = fmaxf(mtB, __shfl_xor_sync(0xffffffffu, mtB, 2));
        float mnA = fmaxf(mA, mtA), mnB = fmaxf(mB, mtB);
        float aA = ex2f(mA - mnA), aB = ex2f(mB - mnB);
        mA = mnA; mB = mnB;
        float rsA = 0.f, rsB = 0.f;
#pragma unroll
        for (int nf = 0; nf < 8; ++nf) {
            c[nf][0] = ex2f(c[nf][0] - mnA);
            c[nf][1] = ex2f(c[nf][1] - mnA);
            c[nf][2] = ex2f(c[nf][2] - mnB);
            c[nf][3] = ex2f(c[nf][3] - mnB);
            rsA += c[nf][0] + c[nf][1];
            rsB += c[nf][2] + c[nf][3];
        }
        lA = lA * aA + rsA;
        lB = lB * aB + rsB;
#pragma unroll
        for (int nf = 0; nf < 16; ++nf) {
            o[nf][0] *= aA; o[nf][1] *= aA;
            o[nf][2] *= aB; o[nf][3] *= aB;
        }

        // ---- O += Ph·Vh (1-pass; P 16x64, V^T 64x128) ----
        const uint32_t stv = st + SK_HI;
#pragma unroll
        for (int kc = 0; kc < 4; ++kc) {
            uint32_t ph[4];
            ph[0] = pack_h2(c[2 * kc][0],     c[2 * kc][1]);
            ph[1] = pack_h2(c[2 * kc][2],     c[2 * kc][3]);
            ph[2] = pack_h2(c[2 * kc + 1][0], c[2 * kc + 1][1]);
            ph[3] = pack_h2(c[2 * kc + 1][2], c[2 * kc + 1][3]);
#pragma unroll
            for (int nf2 = 0; nf2 < 8; ++nf2) {
                uint32_t offV = (uint32_t)((nf2 * 16 + (lane & 7) + ((lane >> 4) << 3)) * FV_ST +
                                           (kc * 16 + (((lane >> 3) & 1) << 3)) * 2);
                uint32_t vh[4];
                ldmatrix_x4(vh, stv + offV);
                mma_f16(o[nf2 * 2], ph, vh[0], vh[1]);
                mma_f16(o[nf2 * 2 + 1], ph, vh[2], vh[3]);
            }
        }
    }

    // ---- epilogue: finish l reduction, normalize, store split ----
    lA += __shfl_xor_sync(0xffffffffu, lA, 1);
    lA += __shfl_xor_sync(0xffffffffu, lA, 2);
    lB += __shfl_xor_sync(0xffffffffu, lB, 1);
    lB += __shfl_xor_sync(0xffffffffu, lB, 2);
    float iA = 1.f / lA, iB = 1.f / lB;
    int rowA = q0 + w * 16 + (lane >> 2);
#pragma unroll
    for (int nf = 0; nf < 16; ++nf) {
        int dcol = nf * 8 + (lane & 3) * 2;
        size_t oA = (((size_t)b * S_ + rowA) * H_ + h) * HD_ + dcol;
        size_t oB = (((size_t)b * S_ + rowA + 8) * H_ + h) * HD_ + dcol;
        store_split2h(athi, atlo, oA, o[nf][0] * iA, o[nf][1] * iA);
        store_split2h(athi, atlo, oB, o[nf][2] * iB, o[nf][3] * iB);
    }
}

// ---------------- host ----------------
extern "C" void kernel_launch(void* const* d_in, const int* in_sizes, int n_in,
                              void* d_out, int out_size) {
    const float* x       = (const float*)d_in[0];
    const float* wq      = (const float*)d_in[1];
    const float* wk      = (const float*)d_in[2];
    const float* wv      = (const float*)d_in[3];
    const float* wo      = (const float*)d_in[4];
    const float* pos_cos = (const float*)d_in[5];
    const float* pos_sin = (const float*)d_in[6];
    float* out = (float*)d_out;

    __half *xhi, *xlo, *wqh, *wkh, *wvh, *woh, *athi, *atlo;
    __half *qhi, *khi, *vthi;
    cudaGetSymbolAddress((void**)&xhi, g_xhi);  cudaGetSymbolAddress((void**)&xlo, g_xlo);
    cudaGetSymbolAddress((void**)&wqh, g_wqh);  cudaGetSymbolAddress((void**)&wkh, g_wkh);
    cudaGetSymbolAddress((void**)&wvh, g_wvh);  cudaGetSymbolAddress((void**)&woh, g_woh);
    cudaGetSymbolAddress((void**)&athi, g_athi); cudaGetSymbolAddress((void**)&atlo, g_atlo);
    cudaGetSymbolAddress((void**)&qhi, g_qhi);  cudaGetSymbolAddress((void**)&khi, g_khi);
    cudaGetSymbolAddress((void**)&vthi, g_vthi);

    const int M = MSZ;          // 8192
    const int KV = KVH_ * HD_;  // 1024
    const float qscale = 0.08838834764831845f * 1.4426950408889634f;  // 1/sqrt(HD)*log2(e)

    // (1) fused conversions
    convert_all<<<dim3(64, 256, 5), dim3(32, 8)>>>(x, wq, wk, wv, wo,
                                                   xhi, xlo, wqh, wkh, wvh, woh);

    cudaFuncSetAttribute(gemm2, cudaFuncAttributeMaxDynamicSharedMemorySize, GEMM_SMEM);

    // (2) Q: RoPE+scale, hi only. (3) K: RoPE, hi only. (4) V: fp16 V^T directly.
    gemm2<<<dim3(D_ / 128, M / 128), 256, GEMM_SMEM>>>(xhi, xlo, wqh, nullptr, qhi, nullptr,
                                                       pos_cos, pos_sin, qscale, M, D_, D_, 1);
    gemm2<<<dim3(KV / 128, M / 128), 256, GEMM_SMEM>>>(xhi, xlo, wkh, nullptr, khi, nullptr,
                                                       pos_cos, pos_sin, 1.0f, M, KV, D_, 1);
    gemm2<<<dim3(KV / 128, M / 128), 256, GEMM_SMEM>>>(xhi, xlo, wvh, nullptr, vthi, nullptr,
                                                       nullptr, nullptr, 0.f, M, KV, D_, 2);

    // (5) flash attention v5 (2 CTAs/SM) -> athi/atlo
    cudaFuncSetAttribute(flash_mma, cudaFuncAttributeMaxDynamicSharedMemorySize, FLASH_SMEM);
    flash_mma<<<dim3(S_ / 64, H_, B_), 128, FLASH_SMEM>>>(qhi, khi, vthi, athi, atlo);

    // (6) output projection -> d_out
    gemm2<<<dim3(D_ / 128, M / 128), 256, GEMM_SMEM>>>(athi, atlo, woh, out, nullptr, nullptr,
                                                       nullptr, nullptr, 0.f, M, D_, D_, 0);
}

// round 15
// speedup vs baseline: 1.2437x; 1.2437x over previous
#include <cuda_runtime.h>
#include <cuda_fp16.h>
#include <math.h>
#include <stdint.h>

#define B_   4
#define S_   2048
#define D_   2048
#define H_   16
#define KVH_ 8
#define HD_  128
#define MSZ  (B_ * S_)          // 8192

// ---------------- scratch (device globals; no allocation allowed) ----------------
__device__ __half g_xhi[(size_t)MSZ * D_];
__device__ __half g_xlo[(size_t)MSZ * D_];
__device__ __half g_wqh[(size_t)D_ * D_];
__device__ __half g_wkh[(size_t)D_ * KVH_ * HD_];
__device__ __half g_wvh[(size_t)D_ * KVH_ * HD_];
__device__ __half g_woh[(size_t)D_ * D_];
__device__ __half g_athi[(size_t)MSZ * D_];
__device__ __half g_atlo[(size_t)MSZ * D_];

__device__ __half g_qhi[(size_t)MSZ * D_];
__device__ __half g_khi[(size_t)MSZ * KVH_ * HD_];
__device__ __half g_vthi[(size_t)MSZ * KVH_ * HD_];     // [b][hk][d][s]

// ================= helpers (baseline PTX only) =================
__device__ __forceinline__ uint32_t smem_u32(const void* p) {
    uint32_t a;
    asm("{ .reg .u64 t; cvta.to.shared.u64 t, %1; cvt.u32.u64 %0, t; }" : "=r"(a) : "l"(p));
    return a;
}
__device__ __forceinline__ void cp_async16(uint32_t dst, const void* src) {
    asm volatile("cp.async.cg.shared.global [%0], [%1], 16;" :: "r"(dst), "l"(src) : "memory");
}
__device__ __forceinline__ void ldmatrix_x4(uint32_t* r, uint32_t addr) {
    asm volatile("ldmatrix.sync.aligned.m8n8.x4.shared.b16 {%0,%1,%2,%3}, [%4];"
                 : "=r"(r[0]), "=r"(r[1]), "=r"(r[2]), "=r"(r[3]) : "r"(addr));
}
__device__ __forceinline__ void mma_f16(float* c, const uint32_t* a, uint32_t b0, uint32_t b1) {
    asm volatile("mma.sync.aligned.m16n8k16.row.col.f32.f16.f16.f32 "
                 "{%0,%1,%2,%3}, {%4,%5,%6,%7}, {%8,%9}, {%0,%1,%2,%3};"
                 : "+f"(c[0]), "+f"(c[1]), "+f"(c[2]), "+f"(c[3])
                 : "r"(a[0]), "r"(a[1]), "r"(a[2]), "r"(a[3]), "r"(b0), "r"(b1));
}
__device__ __forceinline__ float ex2f(float x) {
    float y;
    asm("ex2.approx.ftz.f32 %0, %1;" : "=f"(y) : "f"(x));
    return y;
}
__device__ __forceinline__ uint32_t pack_h2(float f0, float f1) {
    uint32_t r;
    asm("cvt.rn.f16x2.f32 %0, %1, %2;" : "=r"(r) : "f"(f1), "f"(f0));
    return r;
}
__device__ __forceinline__ void store_split2h(__half* hi, __half* lo,
                                              size_t off, float f0, float f1) {
    __half h0 = __float2half_rn(f0), h1 = __float2half_rn(f1);
    *(__half2*)(hi + off) = __halves2half2(h0, h1);
    *(__half2*)(lo + off) = __halves2half2(
        __float2half_rn(f0 - __half2float(h0)),
        __float2half_rn(f1 - __half2float(h1)));
}

// ================= fused conversions (ONE launch) =================
__global__ __launch_bounds__(256) void convert_all(const float* __restrict__ x,
                                                   const float* __restrict__ wq,
                                                   const float* __restrict__ wk,
                                                   const float* __restrict__ wv,
                                                   const float* __restrict__ wo,
                                                   __half* __restrict__ xhi,
                                                   __half* __restrict__ xlo,
                                                   __half* __restrict__ wqh,
                                                   __half* __restrict__ wkh,
                                                   __half* __restrict__ wvh,
                                                   __half* __restrict__ woh) {
    const int z = blockIdx.z;
    const int xq = threadIdx.x, y = threadIdx.y;
    if (z == 4) {
        int r0 = blockIdx.y * 32, c0 = blockIdx.x * 32;
#pragma unroll
        for (int i = 0; i < 32; i += 8) {
            size_t idx = (size_t)(r0 + y + i) * D_ + c0 + xq;
            float f = x[idx];
            __half h = __float2half_rn(f);
            xhi[idx] = h;
            xlo[idx] = __float2half_rn(f - __half2float(h));
        }
        return;
    }
    const float* W; __half* O; int Nd;
    if (z == 0)      { W = wq; O = wqh; Nd = D_; }
    else if (z == 1) { W = wo; O = woh; Nd = D_; }
    else if (z == 2) { W = wk; O = wkh; Nd = KVH_ * HD_; }
    else             { W = wv; O = wvh; Nd = KVH_ * HD_; }
    if (blockIdx.y >= 64u || blockIdx.x >= (unsigned)(Nd / 32)) return;

    __shared__ float t[32][33];
    int k0 = blockIdx.y * 32, n0 = blockIdx.x * 32;
#pragma unroll
    for (int i = 0; i < 32; i += 8)
        t[y + i][xq] = W[(size_t)(k0 + y + i) * Nd + n0 + xq];
    __syncthreads();
#pragma unroll
    for (int i = 0; i < 32; i += 8)
        O[(size_t)(n0 + y + i) * D_ + k0 + xq] = __float2half_rn(t[xq][y + i]);
}

// ================= 2-pass fp16 GEMM: C = (Ahi+Alo)·Bhi^T =================
// mode 0: fp32 C. mode 1: RoPE(+scale) epilogue -> fp16 (lo optional). mode 2: V^T fp16.
// __launch_bounds__(256, 2): cap regs at 128 -> 2 CTAs/SM (occupancy was reg-bound at 1).
#define TILE_B   10240          // 128 rows x 80 bytes
#define STAGE2_B (3 * TILE_B)   // Ah, Al, Bh
#define GEMM_SMEM (2 * STAGE2_B)

__global__ __launch_bounds__(256, 2) void gemm2(const __half* __restrict__ Ahi,
                                                const __half* __restrict__ Alo,
                                                const __half* __restrict__ Bh,
                                                float* __restrict__ C,
                                                __half* __restrict__ Ohi,
                                                __half* __restrict__ Olo,
                                                const float* __restrict__ co,
                                                const float* __restrict__ si,
                                                float scale,
                                                int M, int N, int K, int mode) {
    extern __shared__ __align__(128) char smh[];
    const int tid = threadIdx.x, lane = tid & 31, wid = tid >> 5;
    const int m0 = blockIdx.y * 128, n0 = blockIdx.x * 128;
    const int wm = (wid & 3) * 32, wn = (wid >> 2) * 64;
    const uint32_t sb = smem_u32(smh);

    const __half* gsrc[3];
    gsrc[0] = Ahi + (size_t)m0 * K;
    gsrc[1] = Alo + (size_t)m0 * K;
    gsrc[2] = Bh + (size_t)n0 * K;

    auto load_chunk = [&](int c, int s) {
        const uint32_t st = sb + s * STAGE2_B;
#pragma unroll
        for (int t = 0; t < 6; ++t) {
            int idx = t * 256 + tid;
            int tile = idx >> 9;
            int r = (idx >> 2) & 127;
            int seg = idx & 3;
            uint32_t dst = st + tile * TILE_B + r * 80 + seg * 16;
            cp_async16(dst, gsrc[tile] + (size_t)r * K + c * 32 + seg * 8);
        }
        asm volatile("cp.async.commit_group;" ::: "memory");
    };

    float acc[2][8][4];
#pragma unroll
    for (int mf = 0; mf < 2; ++mf)
#pragma unroll
        for (int nf = 0; nf < 8; ++nf)
#pragma unroll
            for (int e = 0; e < 4; ++e) acc[mf][nf][e] = 0.f;

    const int nch = K / 32;
    load_chunk(0, 0);
    load_chunk(1, 1);

    for (int i = 0; i < nch; ++i) {
        const int s = i & 1;
        if (i + 1 < nch) asm volatile("cp.async.wait_group 1;" ::: "memory");
        else             asm volatile("cp.async.wait_group 0;" ::: "memory");
        __syncthreads();

        const uint32_t st = sb + s * STAGE2_B;
#pragma unroll
        for (int k16 = 0; k16 < 2; ++k16) {
            uint32_t ah[2][4], al[2][4];
#pragma unroll
            for (int mf = 0; mf < 2; ++mf) {
                int rowA = wm + mf * 16 + (lane & 15);
                int kA = k16 * 16 + ((lane >> 4) << 3);
                uint32_t off = (uint32_t)(rowA * 80 + kA * 2);
                ldmatrix_x4(ah[mf], st + off);
                ldmatrix_x4(al[mf], st + TILE_B + off);
            }
            uint32_t bh[4][4];
#pragma unroll
            for (int nf2 = 0; nf2 < 4; ++nf2) {
                int rowB = wn + nf2 * 16 + (lane & 7) + ((lane >> 4) << 3);
                int kB = k16 * 16 + (((lane >> 3) & 1) << 3);
                uint32_t off = (uint32_t)(rowB * 80 + kB * 2);
                ldmatrix_x4(bh[nf2], st + 2 * TILE_B + off);
            }
#pragma unroll
            for (int mf = 0; mf < 2; ++mf)
#pragma unroll
                for (int nf = 0; nf < 8; ++nf) {
                    uint32_t b0 = bh[nf >> 1][(nf & 1) * 2], b1 = bh[nf >> 1][(nf & 1) * 2 + 1];
                    mma_f16(acc[mf][nf], ah[mf], b0, b1);
                    mma_f16(acc[mf][nf], al[mf], b0, b1);
                }
        }
        __syncthreads();
        if (i + 2 < nch) load_chunk(i + 2, s);
    }

    if (mode == 0) {
#pragma unroll
        for (int mf = 0; mf < 2; ++mf) {
            int row = m0 + wm + mf * 16 + (lane >> 2);
#pragma unroll
            for (int nf = 0; nf < 8; ++nf) {
                int col = n0 + wn + nf * 8 + (lane & 3) * 2;
                *(float2*)&C[(size_t)row * N + col] = make_float2(acc[mf][nf][0], acc[mf][nf][1]);
                *(float2*)&C[(size_t)(row + 8) * N + col] = make_float2(acc[mf][nf][2], acc[mf][nf][3]);
            }
        }
    } else if (mode == 1) {
        // RoPE + scale epilogue; store hi (and lo if Olo != null)
#pragma unroll
        for (int mf = 0; mf < 2; ++mf) {
            int row = m0 + wm + mf * 16 + (lane >> 2);
            int s0 = row & (S_ - 1);
            int s1 = (row + 8) & (S_ - 1);
#pragma unroll
            for (int nf = 0; nf < 8; ++nf) {
                int col = n0 + wn + nf * 8 + (lane & 3) * 2;
                int fi = (col & (HD_ - 1)) >> 1;
                float c0 = co[s0 * 64 + fi], sn0 = si[s0 * 64 + fi];
                float c1 = co[s1 * 64 + fi], sn1 = si[s1 * 64 + fi];
                float a0 = acc[mf][nf][0], a1 = acc[mf][nf][1];
                float b0 = acc[mf][nf][2], b1 = acc[mf][nf][3];
                float r00 = (a0 * c0 - a1 * sn0) * scale, r01 = (a0 * sn0 + a1 * c0) * scale;
                float r10 = (b0 * c1 - b1 * sn1) * scale, r11 = (b0 * sn1 + b1 * c1) * scale;
                if (Olo) {
                    store_split2h(Ohi, Olo, (size_t)row * N + col, r00, r01);
                    store_split2h(Ohi, Olo, (size_t)(row + 8) * N + col, r10, r11);
                } else {
                    *(uint32_t*)((__half*)Ohi + (size_t)row * N + col) = pack_h2(r00, r01);
                    *(uint32_t*)((__half*)Ohi + (size_t)(row + 8) * N + col) = pack_h2(r10, r11);
                }
            }
        }
    } else {
        // mode 2: V^T epilogue — acc(row=bs token, col=hk*128+d) -> Ohi[b][hk][d][s]
#pragma unroll
        for (int mf = 0; mf < 2; ++mf) {
            int row = m0 + wm + mf * 16 + (lane >> 2);
#pragma unroll
            for (int rr = 0; rr < 2; ++rr) {
                int r = row + rr * 8;
                int bb = r >> 11, ss = r & (S_ - 1);
#pragma unroll
                for (int nf = 0; nf < 8; ++nf) {
                    int col = n0 + wn + nf * 8 + (lane & 3) * 2;
                    int hk = col >> 7, d = col & (HD_ - 1);
                    size_t base = (((size_t)bb * KVH_ + hk) * HD_ + d) * S_ + ss;
                    Ohi[base]      = __float2half_rn(acc[mf][nf][rr * 2 + 0]);
                    Ohi[base + S_] = __float2half_rn(acc[mf][nf][rr * 2 + 1]);   // d+1 row
                }
            }
        }
    }
}

// ================= flash attention v6: 64 q-rows/CTA, 2-stage, 3 CTAs/SM =================
// CTA: 128 threads (4 warps). KV tiles 64-wide. Double-buffer (2 syncs/tile), 12 warps/SM.
#define FK_ST 272               // K row stride bytes (128 halves + 8 pad)
#define FV_ST 144               // V^T row stride bytes (64 halves + 8 pad)
#define SK_HI 17408             // 64 * 272
#define SV_HI 18432             // 128 * 144
#define FSTAGE (SK_HI + SV_HI)  // 35840
#define NSTG 2
#define FLASH_SMEM (NSTG * FSTAGE)   // 71680 -> 3 CTAs/SM

__global__ __launch_bounds__(128, 3) void flash_mma(
    const __half* __restrict__ qhi,
    const __half* __restrict__ khi,
    const __half* __restrict__ vthi,
    __half* __restrict__ athi, __half* __restrict__ atlo) {
    extern __shared__ __align__(128) char smc[];
    const uint32_t sb = smem_u32(smc);
    const int tid = threadIdx.x, lane = tid & 31, w = tid >> 5;   // w: 0..3
    const int qt = (int)gridDim.x - 1 - (int)blockIdx.x;          // heavy CTAs first
    const int h = blockIdx.y, b = blockIdx.z, hk = h >> 1;
    const int q0 = qt * 64;
    const int ntiles = qt + 1;

    auto load_tile = [&](int j, int s) {
        const uint32_t stb = sb + s * FSTAGE;
#pragma unroll
        for (int t = 0; t < 8; ++t) {
            int idx = t * 128 + tid;          // 64 rows x 16 segs
            int r = idx >> 4, seg = idx & 15;
            size_t go = (((size_t)b * S_ + j * 64 + r) * KVH_ + hk) * HD_ + seg * 8;
            cp_async16(stb + (uint32_t)(r * FK_ST + seg * 16), khi + go);
        }
#pragma unroll
        for (int t = 0; t < 8; ++t) {
            int idx = t * 128 + tid;          // 128 d-rows x 8 segs
            int dd = idx >> 3, seg = idx & 7;
            size_t go = (((size_t)b * KVH_ + hk) * HD_ + dd) * S_ + j * 64 + seg * 8;
            cp_async16(stb + SK_HI + (uint32_t)(dd * FV_ST + seg * 16), vthi + go);
        }
        asm volatile("cp.async.commit_group;" ::: "memory");
    };

    // ---- Q hi load (64 rows) into buffer 0, pull fragments to registers ----
#pragma unroll
    for (int t = 0; t < 8; ++t) {
        int idx = t * 128 + tid;
        int r = idx >> 4, seg = idx & 15;
        size_t go = (((size_t)b * S_ + q0 + r) * H_ + h) * HD_ + seg * 8;
        cp_async16(sb + (uint32_t)(r * FK_ST + seg * 16), qhi + go);
    }
    asm volatile("cp.async.commit_group;" ::: "memory");
    asm volatile("cp.async.wait_group 0;" ::: "memory");
    __syncthreads();
    uint32_t qh[8][4];
#pragma unroll
    for (int k16 = 0; k16 < 8; ++k16) {
        uint32_t offA = (uint32_t)((w * 16 + (lane & 15)) * FK_ST +
                                   (k16 * 16 + ((lane >> 4) << 3)) * 2);
        ldmatrix_x4(qh[k16], sb + offA);
    }
    __syncthreads();   // buffer 0 drained before tile 0 load reuses it

    load_tile(0, 0);
    if (ntiles > 1) load_tile(1, 1);

    float o[16][4];
#pragma unroll
    for (int nf = 0; nf < 16; ++nf)
#pragma unroll
        for (int e = 0; e < 4; ++e) o[nf][e] = 0.f;
    float mA = -1e30f, mB = -1e30f, lA = 0.f, lB = 0.f;   // l: per-lane partials

    for (int i = 0; i < ntiles; ++i) {
        if (i + 1 < ntiles) asm volatile("cp.async.wait_group 1;" ::: "memory");
        else                asm volatile("cp.async.wait_group 0;" ::: "memory");
        __syncthreads();

        const uint32_t st = sb + (i & 1) * FSTAGE;

        // ---- S = Qh·Kh^T (1-pass, 64 cols) ----
        float c[8][4];
#pragma unroll
        for (int nf = 0; nf < 8; ++nf)
#pragma unroll
            for (int e = 0; e < 4; ++e) c[nf][e] = 0.f;

#pragma unroll
        for (int k16 = 0; k16 < 8; ++k16) {
#pragma unroll
            for (int g = 0; g < 4; ++g) {
                uint32_t bh[4];
                uint32_t offB = (uint32_t)((g * 16 + (lane & 7) + ((lane >> 4) << 3)) * FK_ST +
                                           (k16 * 16 + (((lane >> 3) & 1) << 3)) * 2);
                ldmatrix_x4(bh, st + offB);
                mma_f16(c[g * 2], qh[k16], bh[0], bh[1]);
                mma_f16(c[g * 2 + 1], qh[k16], bh[2], bh[3]);
            }
        }

        // ---- causal mask (diagonal tile only) ----
        if (i == qt) {
            int rowA = q0 + w * 16 + (lane >> 2);
            int colb = i * 64 + (lane & 3) * 2;
#pragma unroll
            for (int nf = 0; nf < 8; ++nf) {
                int c0 = colb + nf * 8, c1 = c0 + 1;
                if (c0 > rowA) c[nf][0] = -1e30f;
                if (c1 > rowA) c[nf][1] = -1e30f;
                if (c0 > rowA + 8) c[nf][2] = -1e30f;
                if (c1 > rowA + 8) c[nf][3] = -1e30f;
            }
        }

        // ---- online softmax (exp2 domain); l kept as per-lane partials ----
        float mtA = -1e30f, mtB = -1e30f;
#pragma unroll
        for (int nf = 0; nf < 8; ++nf) {
            mtA = fmaxf(mtA, fmaxf(c[nf][0], c[nf][1]));
            mtB = fmaxf(mtB, fmaxf(c[nf][2], c[nf][3]));
        }
        mtA = fmaxf(mtA, __shfl_xor_sync(0xffffffffu, mtA, 1));
        mtA = fmaxf(mtA, __shfl_xor_sync(0xffffffffu, mtA, 2));
        mtB = fmaxf(mtB, __shfl_xor_sync(0xffffffffu, mtB, 1));
        mtB = fmaxf(mtB, __shfl_xor_sync(0xffffffffu, mtB, 2));
        float mnA = fmaxf(mA, mtA), mnB = fmaxf(mB, mtB);
        float aA = ex2f(mA - mnA), aB = ex2f(mB - mnB);
        mA = mnA; mB = mnB;
        float rsA = 0.f, rsB = 0.f;
#pragma unroll
        for (int nf = 0; nf < 8; ++nf) {
            c[nf][0] = ex2f(c[nf][0] - mnA);
            c[nf][1] = ex2f(c[nf][1] - mnA);
            c[nf][2] = ex2f(c[nf][2] - mnB);
            c[nf][3] = ex2f(c[nf][3] - mnB);
            rsA += c[nf][0] + c[nf][1];
            rsB += c[nf][2] + c[nf][3];
        }
        lA = lA * aA + rsA;
        lB = lB * aB + rsB;
#pragma unroll
        for (int nf = 0; nf < 16; ++nf) {
            o[nf][0] *= aA; o[nf][1] *= aA;
            o[nf][2] *= aB; o[nf][3] *= aB;
        }

        // ---- O += Ph·Vh (1-pass; P 16x64, V^T 64x128) ----
        const uint32_t stv = st + SK_HI;
#pragma unroll
        for (int kc = 0; kc < 4; ++kc) {
            uint32_t ph[4];
            ph[0] = pack_h2(c[2 * kc][0],     c[2 * kc][1]);
            ph[1] = pack_h2(c[2 * kc][2],     c[2 * kc][3]);
            ph[2] = pack_h2(c[2 * kc + 1][0], c[2 * kc + 1][1]);
            ph[3] = pack_h2(c[2 * kc + 1][2], c[2 * kc + 1][3]);
#pragma unroll
            for (int nf2 = 0; nf2 < 8; ++nf2) {
                uint32_t offV = (uint32_t)((nf2 * 16 + (lane & 7) + ((lane >> 4) << 3)) * FV_ST +
                                           (kc * 16 + (((lane >> 3) & 1) << 3)) * 2);
                uint32_t vh[4];
                ldmatrix_x4(vh, stv + offV);
                mma_f16(o[nf2 * 2], ph, vh[0], vh[1]);
                mma_f16(o[nf2 * 2 + 1], ph, vh[2], vh[3]);
            }
        }

        // ---- prefetch tile i+2 into buffer i&1 (after all warps finished tile i) ----
        if (i + 2 < ntiles) {
            __syncthreads();
            load_tile(i + 2, i & 1);
        }
    }

    // ---- epilogue: finish l reduction, normalize, store split ----
    lA += __shfl_xor_sync(0xffffffffu, lA, 1);
    lA += __shfl_xor_sync(0xffffffffu, lA, 2);
    lB += __shfl_xor_sync(0xffffffffu, lB, 1);
    lB += __shfl_xor_sync(0xffffffffu, lB, 2);
    float iA = 1.f / lA, iB = 1.f / lB;
    int rowA = q0 + w * 16 + (lane >> 2);
#pragma unroll
    for (int nf = 0; nf < 16; ++nf) {
        int dcol = nf * 8 + (lane & 3) * 2;
        size_t oA = (((size_t)b * S_ + rowA) * H_ + h) * HD_ + dcol;
        size_t oB = (((size_t)b * S_ + rowA + 8) * H_ + h) * HD_ + dcol;
        store_split2h(athi, atlo, oA, o[nf][0] * iA, o[nf][1] * iA);
        store_split2h(athi, atlo, oB, o[nf][2] * iB, o[nf][3] * iB);
    }
}

// ---------------- host ----------------
extern "C" void kernel_launch(void* const* d_in, const int* in_sizes, int n_in,
                              void* d_out, int out_size) {
    const float* x       = (const float*)d_in[0];
    const float* wq      = (const float*)d_in[1];
    const float* wk      = (const float*)d_in[2];
    const float* wv      = (const float*)d_in[3];
    const float* wo      = (const float*)d_in[4];
    const float* pos_cos = (const float*)d_in[5];
    const float* pos_sin = (const float*)d_in[6];
    float* out = (float*)d_out;

    __half *xhi, *xlo, *wqh, *wkh, *wvh, *woh, *athi, *atlo;
    __half *qhi, *khi, *vthi;
    cudaGetSymbolAddress((void**)&xhi, g_xhi);  cudaGetSymbolAddress((void**)&xlo, g_xlo);
    cudaGetSymbolAddress((void**)&wqh, g_wqh);  cudaGetSymbolAddress((void**)&wkh, g_wkh);
    cudaGetSymbolAddress((void**)&wvh, g_wvh);  cudaGetSymbolAddress((void**)&woh, g_woh);
    cudaGetSymbolAddress((void**)&athi, g_athi); cudaGetSymbolAddress((void**)&atlo, g_atlo);
    cudaGetSymbolAddress((void**)&qhi, g_qhi);  cudaGetSymbolAddress((void**)&khi, g_khi);
    cudaGetSymbolAddress((void**)&vthi, g_vthi);

    const int M = MSZ;          // 8192
    const int KV = KVH_ * HD_;  // 1024
    const float qscale = 0.08838834764831845f * 1.4426950408889634f;  // 1/sqrt(HD)*log2(e)

    // (1) fused conversions
    convert_all<<<dim3(64, 256, 5), dim3(32, 8)>>>(x, wq, wk, wv, wo,
                                                   xhi, xlo, wqh, wkh, wvh, woh);

    cudaFuncSetAttribute(gemm2, cudaFuncAttributeMaxDynamicSharedMemorySize, GEMM_SMEM);

    // (2) Q: RoPE+scale, hi only. (3) K: RoPE, hi only. (4) V: fp16 V^T directly.
    gemm2<<<dim3(D_ / 128, M / 128), 256, GEMM_SMEM>>>(xhi, xlo, wqh, nullptr, qhi, nullptr,
                                                       pos_cos, pos_sin, qscale, M, D_, D_, 1);
    gemm2<<<dim3(KV / 128, M / 128), 256, GEMM_SMEM>>>(xhi, xlo, wkh, nullptr, khi, nullptr,
                                                       pos_cos, pos_sin, 1.0f, M, KV, D_, 1);
    gemm2<<<dim3(KV / 128, M / 128), 256, GEMM_SMEM>>>(xhi, xlo, wvh, nullptr, vthi, nullptr,
                                                       nullptr, nullptr, 0.f, M, KV, D_, 2);

    // (5) flash attention v6 (3 CTAs/SM) -> athi/atlo
    cudaFuncSetAttribute(flash_mma, cudaFuncAttributeMaxDynamicSharedMemorySize, FLASH_SMEM);
    flash_mma<<<dim3(S_ / 64, H_, B_), 128, FLASH_SMEM>>>(qhi, khi, vthi, athi, atlo);

    // (6) output projection -> d_out
    gemm2<<<dim3(D_ / 128, M / 128), 256, GEMM_SMEM>>>(athi, atlo, woh, out, nullptr, nullptr,
                                                       nullptr, nullptr, 0.f, M, D_, D_, 0);
}

// round 17
// speedup vs baseline: 1.2738x; 1.0242x over previous
#include <cuda_runtime.h>
#include <cuda_fp16.h>
#include <math.h>
#include <stdint.h>

#define B_   4
#define S_   2048
#define D_   2048
#define H_   16
#define KVH_ 8
#define HD_  128
#define MSZ  (B_ * S_)          // 8192

// ---------------- scratch (device globals; no allocation allowed) ----------------
__device__ __half g_xhi[(size_t)MSZ * D_];
__device__ __half g_xlo[(size_t)MSZ * D_];
__device__ __half g_wqh[(size_t)D_ * D_];
__device__ __half g_wkh[(size_t)D_ * KVH_ * HD_];
__device__ __half g_wvh[(size_t)D_ * KVH_ * HD_];
__device__ __half g_woh[(size_t)D_ * D_];
__device__ __half g_athi[(size_t)MSZ * D_];
__device__ __half g_atlo[(size_t)MSZ * D_];

__device__ __half g_qhi[(size_t)MSZ * D_];
__device__ __half g_khi[(size_t)MSZ * KVH_ * HD_];
__device__ __half g_vthi[(size_t)MSZ * KVH_ * HD_];     // [b][hk][d][s]

// ================= helpers (baseline PTX only) =================
__device__ __forceinline__ uint32_t smem_u32(const void* p) {
    uint32_t a;
    asm("{ .reg .u64 t; cvta.to.shared.u64 t, %1; cvt.u32.u64 %0, t; }" : "=r"(a) : "l"(p));
    return a;
}
__device__ __forceinline__ void cp_async16(uint32_t dst, const void* src) {
    asm volatile("cp.async.cg.shared.global [%0], [%1], 16;" :: "r"(dst), "l"(src) : "memory");
}
__device__ __forceinline__ void ldmatrix_x4(uint32_t* r, uint32_t addr) {
    asm volatile("ldmatrix.sync.aligned.m8n8.x4.shared.b16 {%0,%1,%2,%3}, [%4];"
                 : "=r"(r[0]), "=r"(r[1]), "=r"(r[2]), "=r"(r[3]) : "r"(addr));
}
__device__ __forceinline__ void mma_f16(float* c, const uint32_t* a, uint32_t b0, uint32_t b1) {
    asm volatile("mma.sync.aligned.m16n8k16.row.col.f32.f16.f16.f32 "
                 "{%0,%1,%2,%3}, {%4,%5,%6,%7}, {%8,%9}, {%0,%1,%2,%3};"
                 : "+f"(c[0]), "+f"(c[1]), "+f"(c[2]), "+f"(c[3])
                 : "r"(a[0]), "r"(a[1]), "r"(a[2]), "r"(a[3]), "r"(b0), "r"(b1));
}
__device__ __forceinline__ float ex2f(float x) {
    float y;
    asm("ex2.approx.ftz.f32 %0, %1;" : "=f"(y) : "f"(x));
    return y;
}
__device__ __forceinline__ uint32_t pack_h2(float f0, float f1) {
    uint32_t r;
    asm("cvt.rn.f16x2.f32 %0, %1, %2;" : "=r"(r) : "f"(f1), "f"(f0));
    return r;
}
__device__ __forceinline__ void store_split2h(__half* hi, __half* lo,
                                              size_t off, float f0, float f1) {
    __half h0 = __float2half_rn(f0), h1 = __float2half_rn(f1);
    *(__half2*)(hi + off) = __halves2half2(h0, h1);
    *(__half2*)(lo + off) = __halves2half2(
        __float2half_rn(f0 - __half2float(h0)),
        __float2half_rn(f1 - __half2float(h1)));
}

// ================= weight conversions (launch #1) =================
// z=0: wq, z=1: wo, z=2: wk, z=3: wv — transpose + fp16 round
__global__ __launch_bounds__(256) void convert_w(const float* __restrict__ wq,
                                                 const float* __restrict__ wk,
                                                 const float* __restrict__ wv,
                                                 const float* __restrict__ wo,
                                                 __half* __restrict__ wqh,
                                                 __half* __restrict__ wkh,
                                                 __half* __restrict__ wvh,
                                                 __half* __restrict__ woh) {
    const int z = blockIdx.z;
    const int xq = threadIdx.x, y = threadIdx.y;
    const float* W; __half* O; int Nd;
    if (z == 0)      { W = wq; O = wqh; Nd = D_; }
    else if (z == 1) { W = wo; O = woh; Nd = D_; }
    else if (z == 2) { W = wk; O = wkh; Nd = KVH_ * HD_; }
    else             { W = wv; O = wvh; Nd = KVH_ * HD_; }
    if (blockIdx.x >= (unsigned)(Nd / 32)) return;

    __shared__ float t[32][33];
    int k0 = blockIdx.y * 32, n0 = blockIdx.x * 32;
#pragma unroll
    for (int i = 0; i < 32; i += 8)
        t[y + i][xq] = W[(size_t)(k0 + y + i) * Nd + n0 + xq];
    __syncthreads();
#pragma unroll
    for (int i = 0; i < 32; i += 8)
        O[(size_t)(n0 + y + i) * D_ + k0 + xq] = __float2half_rn(t[xq][y + i]);
}

// ================= x hi/lo split (launch #2) =================
__global__ __launch_bounds__(256) void convert_x(const float* __restrict__ x,
                                                 __half* __restrict__ xhi,
                                                 __half* __restrict__ xlo) {
    size_t i = (size_t)blockIdx.x * blockDim.x + threadIdx.x;
    float f = x[i];
    __half h = __float2half_rn(f);
    xhi[i] = h;
    xlo[i] = __float2half_rn(f - __half2float(h));
}

// ================= 2-pass fp16 GEMM, K-chunk 64: C = (Ahi+Alo)·Bhi^T =================
// mode 0: fp32 C. mode 1: RoPE(+scale) -> fp16 (lo optional). mode 2: V^T fp16.
// 2 CTAs/SM (regs capped 128); 2-stage double buffer, 64-deep K chunks (32 iterations).
#define T64_ST  144             // row stride bytes (64 halves + 8 pad)
#define TILE64  18432           // 128 * 144
#define STG64   (3 * TILE64)    // Ah, Al, Bh = 55296
#define GEMM_SMEM (2 * STG64)   // 110592 -> 2 CTAs = 216KB

__global__ __launch_bounds__(256, 2) void gemm2(const __half* __restrict__ Ahi,
                                                const __half* __restrict__ Alo,
                                                const __half* __restrict__ Bh,
                                                float* __restrict__ C,
                                                __half* __restrict__ Ohi,
                                                __half* __restrict__ Olo,
                                                const float* __restrict__ co,
                                                const float* __restrict__ si,
                                                float scale,
                                                int M, int N, int K, int mode) {
    extern __shared__ __align__(128) char smh[];
    const int tid = threadIdx.x, lane = tid & 31, wid = tid >> 5;
    const int m0 = blockIdx.y * 128, n0 = blockIdx.x * 128;
    const int wm = (wid & 3) * 32, wn = (wid >> 2) * 64;
    const uint32_t sb = smem_u32(smh);

    const __half* gsrc[3];
    gsrc[0] = Ahi + (size_t)m0 * K;
    gsrc[1] = Alo + (size_t)m0 * K;
    gsrc[2] = Bh + (size_t)n0 * K;

    auto load_chunk = [&](int c, int s) {
        const uint32_t st = sb + s * STG64;
#pragma unroll
        for (int t = 0; t < 12; ++t) {
            int idx = t * 256 + tid;          // 0..3071
            int tile = idx >> 10;             // 0..2
            int r = (idx >> 3) & 127;         // row
            int seg = idx & 7;                // 16B segment (8 per 128B row)
            uint32_t dst = st + tile * TILE64 + r * T64_ST + seg * 16;
            cp_async16(dst, gsrc[tile] + (size_t)r * K + c * 64 + seg * 8);
        }
        asm volatile("cp.async.commit_group;" ::: "memory");
    };

    float acc[2][8][4];
#pragma unroll
    for (int mf = 0; mf < 2; ++mf)
#pragma unroll
        for (int nf = 0; nf < 8; ++nf)
#pragma unroll
            for (int e = 0; e < 4; ++e) acc[mf][nf][e] = 0.f;

    const int nch = K / 64;     // 32
    load_chunk(0, 0);
    load_chunk(1, 1);

    for (int i = 0; i < nch; ++i) {
        const int s = i & 1;
        if (i + 1 < nch) asm volatile("cp.async.wait_group 1;" ::: "memory");
        else             asm volatile("cp.async.wait_group 0;" ::: "memory");
        __syncthreads();

        const uint32_t st = sb + s * STG64;
#pragma unroll
        for (int k16 = 0; k16 < 4; ++k16) {
            uint32_t ah[2][4], al[2][4];
#pragma unroll
            for (int mf = 0; mf < 2; ++mf) {
                int rowA = wm + mf * 16 + (lane & 15);
                int kA = k16 * 16 + ((lane >> 4) << 3);
                uint32_t off = (uint32_t)(rowA * T64_ST + kA * 2);
                ldmatrix_x4(ah[mf], st + off);
                ldmatrix_x4(al[mf], st + TILE64 + off);
            }
            uint32_t bh[4][4];
#pragma unroll
            for (int nf2 = 0; nf2 < 4; ++nf2) {
                int rowB = wn + nf2 * 16 + (lane & 7) + ((lane >> 4) << 3);
                int kB = k16 * 16 + (((lane >> 3) & 1) << 3);
                uint32_t off = (uint32_t)(rowB * T64_ST + kB * 2);
                ldmatrix_x4(bh[nf2], st + 2 * TILE64 + off);
            }
#pragma unroll
            for (int mf = 0; mf < 2; ++mf)
#pragma unroll
                for (int nf = 0; nf < 8; ++nf) {
                    uint32_t b0 = bh[nf >> 1][(nf & 1) * 2], b1 = bh[nf >> 1][(nf & 1) * 2 + 1];
                    mma_f16(acc[mf][nf], ah[mf], b0, b1);
                    mma_f16(acc[mf][nf], al[mf], b0, b1);
                }
        }
        __syncthreads();
        if (i + 2 < nch) load_chunk(i + 2, s);
    }

    if (mode == 0) {
#pragma unroll
        for (int mf = 0; mf < 2; ++mf) {
            int row = m0 + wm + mf * 16 + (lane >> 2);
#pragma unroll
            for (int nf = 0; nf < 8; ++nf) {
                int col = n0 + wn + nf * 8 + (lane & 3) * 2;
                *(float2*)&C[(size_t)row * N + col] = make_float2(acc[mf][nf][0], acc[mf][nf][1]);
                *(float2*)&C[(size_t)(row + 8) * N + col] = make_float2(acc[mf][nf][2], acc[mf][nf][3]);
            }
        }
    } else if (mode == 1) {
        // RoPE + scale epilogue; store hi (and lo if Olo != null)
#pragma unroll
        for (int mf = 0; mf < 2; ++mf) {
            int row = m0 + wm + mf * 16 + (lane >> 2);
            int s0 = row & (S_ - 1);
            int s1 = (row + 8) & (S_ - 1);
#pragma unroll
            for (int nf = 0; nf < 8; ++nf) {
                int col = n0 + wn + nf * 8 + (lane & 3) * 2;
                int fi = (col & (HD_ - 1)) >> 1;
                float c0 = co[s0 * 64 + fi], sn0 = si[s0 * 64 + fi];
                float c1 = co[s1 * 64 + fi], sn1 = si[s1 * 64 + fi];
                float a0 = acc[mf][nf][0], a1 = acc[mf][nf][1];
                float b0 = acc[mf][nf][2], b1 = acc[mf][nf][3];
                float r00 = (a0 * c0 - a1 * sn0) * scale, r01 = (a0 * sn0 + a1 * c0) * scale;
                float r10 = (b0 * c1 - b1 * sn1) * scale, r11 = (b0 * sn1 + b1 * c1) * scale;
                if (Olo) {
                    store_split2h(Ohi, Olo, (size_t)row * N + col, r00, r01);
                    store_split2h(Ohi, Olo, (size_t)(row + 8) * N + col, r10, r11);
                } else {
                    *(uint32_t*)((__half*)Ohi + (size_t)row * N + col) = pack_h2(r00, r01);
                    *(uint32_t*)((__half*)Ohi + (size_t)(row + 8) * N + col) = pack_h2(r10, r11);
                }
            }
        }
    } else {
        // mode 2: V^T epilogue — acc(row=bs token, col=hk*128+d) -> Ohi[b][hk][d][s]
#pragma unroll
        for (int mf = 0; mf < 2; ++mf) {
            int row = m0 + wm + mf * 16 + (lane >> 2);
#pragma unroll
            for (int rr = 0; rr < 2; ++rr) {
                int r = row + rr * 8;
                int bb = r >> 11, ss = r & (S_ - 1);
#pragma unroll
                for (int nf = 0; nf < 8; ++nf) {
                    int col = n0 + wn + nf * 8 + (lane & 3) * 2;
                    int hk = col >> 7, d = col & (HD_ - 1);
                    size_t base = (((size_t)bb * KVH_ + hk) * HD_ + d) * S_ + ss;
                    Ohi[base]      = __float2half_rn(acc[mf][nf][rr * 2 + 0]);
                    Ohi[base + S_] = __float2half_rn(acc[mf][nf][rr * 2 + 1]);   // d+1 row
                }
            }
        }
    }
}

// ================= flash attention v6 (proven): 64 q-rows/CTA, 2-stage, 3 CTAs/SM =================
#define FK_ST 272               // K row stride bytes (128 halves + 8 pad)
#define FV_ST 144               // V^T row stride bytes (64 halves + 8 pad)
#define SK_HI 17408             // 64 * 272
#define SV_HI 18432             // 128 * 144
#define FSTAGE (SK_HI + SV_HI)  // 35840
#define NSTG 2
#define FLASH_SMEM (NSTG * FSTAGE)   // 71680 -> 3 CTAs/SM

__global__ __launch_bounds__(128, 3) void flash_mma(
    const __half* __restrict__ qhi,
    const __half* __restrict__ khi,
    const __half* __restrict__ vthi,
    __half* __restrict__ athi, __half* __restrict__ atlo) {
    extern __shared__ __align__(128) char smc[];
    const uint32_t sb = smem_u32(smc);
    const int tid = threadIdx.x, lane = tid & 31, w = tid >> 5;
    const int qt = (int)gridDim.x - 1 - (int)blockIdx.x;
    const int h = blockIdx.y, b = blockIdx.z, hk = h >> 1;
    const int q0 = qt * 64;
    const int ntiles = qt + 1;

    auto load_tile = [&](int j, int s) {
        const uint32_t stb = sb + s * FSTAGE;
#pragma unroll
        for (int t = 0; t < 8; ++t) {
            int idx = t * 128 + tid;
            int r = idx >> 4, seg = idx & 15;
            size_t go = (((size_t)b * S_ + j * 64 + r) * KVH_ + hk) * HD_ + seg * 8;
            cp_async16(stb + (uint32_t)(r * FK_ST + seg * 16), khi + go);
        }
#pragma unroll
        for (int t = 0; t < 8; ++t) {
            int idx = t * 128 + tid;
            int dd = idx >> 3, seg = idx & 7;
            size_t go = (((size_t)b * KVH_ + hk) * HD_ + dd) * S_ + j * 64 + seg * 8;
            cp_async16(stb + SK_HI + (uint32_t)(dd * FV_ST + seg * 16), vthi + go);
        }
        asm volatile("cp.async.commit_group;" ::: "memory");
    };

    // ---- Q hi load into buffer 0, pull fragments to registers ----
#pragma unroll
    for (int t = 0; t < 8; ++t) {
        int idx = t * 128 + tid;
        int r = idx >> 4, seg = idx & 15;
        size_t go = (((size_t)b * S_ + q0 + r) * H_ + h) * HD_ + seg * 8;
        cp_async16(sb + (uint32_t)(r * FK_ST + seg * 16), qhi + go);
    }
    asm volatile("cp.async.commit_group;" ::: "memory");
    asm volatile("cp.async.wait_group 0;" ::: "memory");
    __syncthreads();
    uint32_t qh[8][4];
#pragma unroll
    for (int k16 = 0; k16 < 8; ++k16) {
        uint32_t offA = (uint32_t)((w * 16 + (lane & 15)) * FK_ST +
                                   (k16 * 16 + ((lane >> 4) << 3)) * 2);
        ldmatrix_x4(qh[k16], sb + offA);
    }
    __syncthreads();

    load_tile(0, 0);
    if (ntiles > 1) load_tile(1, 1);

    float o[16][4];
#pragma unroll
    for (int nf = 0; nf < 16; ++nf)
#pragma unroll
        for (int e = 0; e < 4; ++e) o[nf][e] = 0.f;
    float mA = -1e30f, mB = -1e30f, lA = 0.f, lB = 0.f;

    for (int i = 0; i < ntiles; ++i) {
        if (i + 1 < ntiles) asm volatile("cp.async.wait_group 1;" ::: "memory");
        else                asm volatile("cp.async.wait_group 0;" ::: "memory");
        __syncthreads();

        const uint32_t st = sb + (i & 1) * FSTAGE;

        float c[8][4];
#pragma unroll
        for (int nf = 0; nf < 8; ++nf)
#pragma unroll
            for (int e = 0; e < 4; ++e) c[nf][e] = 0.f;

#pragma unroll
        for (int k16 = 0; k16 < 8; ++k16) {
#pragma unroll
            for (int g = 0; g < 4; ++g) {
                uint32_t bh[4];
                uint32_t offB = (uint32_t)((g * 16 + (lane & 7) + ((lane >> 4) << 3)) * FK_ST +
                                           (k16 * 16 + (((lane >> 3) & 1) << 3)) * 2);
                ldmatrix_x4(bh, st + offB);
                mma_f16(c[g * 2], qh[k16], bh[0], bh[1]);
                mma_f16(c[g * 2 + 1], qh[k16], bh[2], bh[3]);
            }
        }

        if (i == qt) {
            int rowA = q0 + w * 16 + (lane >> 2);
            int colb = i * 64 + (lane & 3) * 2;
#pragma unroll
            for (int nf = 0; nf < 8; ++nf) {
                int c0 = colb + nf * 8, c1 = c0 + 1;
                if (c0 > rowA) c[nf][0] = -1e30f;
                if (c1 > rowA) c[nf][1] = -1e30f;
                if (c0 > rowA + 8) c[nf][2] = -1e30f;
                if (c1 > rowA + 8) c[nf][3] = -1e30f;
            }
        }

        float mtA = -1e30f, mtB = -1e30f;
#pragma unroll
        for (int nf = 0; nf < 8; ++nf) {
            mtA = fmaxf(mtA, fmaxf(c[nf][0], c[nf][1]));
            mtB = fmaxf(mtB, fmaxf(c[nf][2], c[nf][3]));
        }
        mtA = fmaxf(mtA, __shfl_xor_sync(0xffffffffu, mtA, 1));
        mtA = fmaxf(mtA, __shfl_xor_sync(0xffffffffu, mtA, 2));
        mtB = fmaxf(mtB, __shfl_xor_sync(0xffffffffu, mtB, 1));
        mtB = fmaxf(mtB, __shfl_xor_sync(0xffffffffu, mtB, 2));
        float mnA = fmaxf(mA, mtA), mnB = fmaxf(mB, mtB);
        float aA = ex2f(mA - mnA), aB = ex2f(mB - mnB);
        mA = mnA; mB = mnB;
        float rsA = 0.f, rsB = 0.f;
#pragma unroll
        for (int nf = 0; nf < 8; ++nf) {
            c[nf][0] = ex2f(c[nf][0] - mnA);
            c[nf][1] = ex2f(c[nf][1] - mnA);
            c[nf][2] = ex2f(c[nf][2] - mnB);
            c[nf][3] = ex2f(c[nf][3] - mnB);
            rsA += c[nf][0] + c[nf][1];
            rsB += c[nf][2] + c[nf][3];
        }
        lA = lA * aA + rsA;
        lB = lB * aB + rsB;
#pragma unroll
        for (int nf = 0; nf < 16; ++nf) {
            o[nf][0] *= aA; o[nf][1] *= aA;
            o[nf][2] *= aB; o[nf][3] *= aB;
        }

        const uint32_t stv = st + SK_HI;
#pragma unroll
        for (int kc = 0; kc < 4; ++kc) {
            uint32_t ph[4];
            ph[0] = pack_h2(c[2 * kc][0],     c[2 * kc][1]);
            ph[1] = pack_h2(c[2 * kc][2],     c[2 * kc][3]);
            ph[2] = pack_h2(c[2 * kc + 1][0], c[2 * kc + 1][1]);
            ph[3] = pack_h2(c[2 * kc + 1][2], c[2 * kc + 1][3]);
#pragma unroll
            for (int nf2 = 0; nf2 < 8; ++nf2) {
                uint32_t offV = (uint32_t)((nf2 * 16 + (lane & 7) + ((lane >> 4) << 3)) * FV_ST +
                                           (kc * 16 + (((lane >> 3) & 1) << 3)) * 2);
                uint32_t vh[4];
                ldmatrix_x4(vh, stv + offV);
                mma_f16(o[nf2 * 2], ph, vh[0], vh[1]);
                mma_f16(o[nf2 * 2 + 1], ph, vh[2], vh[3]);
            }
        }

        if (i + 2 < ntiles) {
            __syncthreads();
            load_tile(i + 2, i & 1);
        }
    }

    lA += __shfl_xor_sync(0xffffffffu, lA, 1);
    lA += __shfl_xor_sync(0xffffffffu, lA, 2);
    lB += __shfl_xor_sync(0xffffffffu, lB, 1);
    lB += __shfl_xor_sync(0xffffffffu, lB, 2);
    float iA = 1.f / lA, iB = 1.f / lB;
    int rowA = q0 + w * 16 + (lane >> 2);
#pragma unroll
    for (int nf = 0; nf < 16; ++nf) {
        int dcol = nf * 8 + (lane & 3) * 2;
        size_t oA = (((size_t)b * S_ + rowA) * H_ + h) * HD_ + dcol;
        size_t oB = (((size_t)b * S_ + rowA + 8) * H_ + h) * HD_ + dcol;
        store_split2h(athi, atlo, oA, o[nf][0] * iA, o[nf][1] * iA);
        store_split2h(athi, atlo, oB, o[nf][2] * iB, o[nf][3] * iB);
    }
}

// ---------------- host ----------------
extern "C" void kernel_launch(void* const* d_in, const int* in_sizes, int n_in,
                              void* d_out, int out_size) {
    const float* x       = (const float*)d_in[0];
    const float* wq      = (const float*)d_in[1];
    const float* wk      = (const float*)d_in[2];
    const float* wv      = (const float*)d_in[3];
    const float* wo      = (const float*)d_in[4];
    const float* pos_cos = (const float*)d_in[5];
    const float* pos_sin = (const float*)d_in[6];
    float* out = (float*)d_out;

    __half *xhi, *xlo, *wqh, *wkh, *wvh, *woh, *athi, *atlo;
    __half *qhi, *khi, *vthi;
    cudaGetSymbolAddress((void**)&xhi, g_xhi);  cudaGetSymbolAddress((void**)&xlo, g_xlo);
    cudaGetSymbolAddress((void**)&wqh, g_wqh);  cudaGetSymbolAddress((void**)&wkh, g_wkh);
    cudaGetSymbolAddress((void**)&wvh, g_wvh);  cudaGetSymbolAddress((void**)&woh, g_woh);
    cudaGetSymbolAddress((void**)&athi, g_athi); cudaGetSymbolAddress((void**)&atlo, g_atlo);
    cudaGetSymbolAddress((void**)&qhi, g_qhi);  cudaGetSymbolAddress((void**)&khi, g_khi);
    cudaGetSymbolAddress((void**)&vthi, g_vthi);

    const int M = MSZ;          // 8192
    const int KV = KVH_ * HD_;  // 1024
    const float qscale = 0.08838834764831845f * 1.4426950408889634f;  // 1/sqrt(HD)*log2(e)

    // (1) weight conversions, (2) x split  [split so flash is launch #6 for ncu]
    convert_w<<<dim3(64, 64, 4), dim3(32, 8)>>>(wq, wk, wv, wo, wqh, wkh, wvh, woh);
    convert_x<<<(unsigned)(((size_t)M * D_) / 256), 256>>>(x, xhi, xlo);

    cudaFuncSetAttribute(gemm2, cudaFuncAttributeMaxDynamicSharedMemorySize, GEMM_SMEM);

    // (3) Q: RoPE+scale hi. (4) K: RoPE hi. (5) V -> V^T fp16.
    gemm2<<<dim3(D_ / 128, M / 128), 256, GEMM_SMEM>>>(xhi, xlo, wqh, nullptr, qhi, nullptr,
                                                       pos_cos, pos_sin, qscale, M, D_, D_, 1);
    gemm2<<<dim3(KV / 128, M / 128), 256, GEMM_SMEM>>>(xhi, xlo, wkh, nullptr, khi, nullptr,
                                                       pos_cos, pos_sin, 1.0f, M, KV, D_, 1);
    gemm2<<<dim3(KV / 128, M / 128), 256, GEMM_SMEM>>>(xhi, xlo, wvh, nullptr, vthi, nullptr,
                                                       nullptr, nullptr, 0.f, M, KV, D_, 2);

    // (6) flash attention (3 CTAs/SM) -> athi/atlo   [ncu capture slot]
    cudaFuncSetAttribute(flash_mma, cudaFuncAttributeMaxDynamicSharedMemorySize, FLASH_SMEM);
    flash_mma<<<dim3(S_ / 64, H_, B_), 128, FLASH_SMEM>>>(qhi, khi, vthi, athi, atlo);

    // (7) output projection -> d_out
    gemm2<<<dim3(D_ / 128, M / 128), 256, GEMM_SMEM>>>(athi, atlo, woh, out, nullptr, nullptr,
                                                       nullptr, nullptr, 0.f, M, D_, D_, 0);
}